// round 1
// baseline (speedup 1.0000x reference)
#include <cuda_runtime.h>
#include <math.h>

#define BATCH 65536
#define DIN   64
#define HID   512

// Scratch (allocation-free rule: __device__ globals)
__device__ float g_h0[(size_t)BATCH * HID];
__device__ float g_h1[(size_t)BATCH * HID];
__device__ float g_da[(size_t)BATCH * HID];
__device__ float g_db[(size_t)BATCH * HID];
__device__ float g_W1t[HID * HID];
__device__ float g_W2t[HID * HID];
__device__ float g_W0t[HID * DIN];

enum { EPI_TANH = 0, EPI_DA2 = 1, EPI_MULT = 2, EPI_SYMP = 3 };

// Tiled transpose: out[C][R] = in[R][C]^T
__global__ void transpose_k(const float* __restrict__ in, float* __restrict__ out,
                            int R, int C) {
    __shared__ float tile[32][33];
    int c0 = blockIdx.x * 32, r0 = blockIdx.y * 32;
    int tx = threadIdx.x, ty = threadIdx.y;  // blockDim (32, 8)
#pragma unroll
    for (int i = 0; i < 32; i += 8) {
        int r = r0 + ty + i, c = c0 + tx;
        if (r < R && c < C) tile[ty + i][tx] = in[(size_t)r * C + c];
    }
    __syncthreads();
#pragma unroll
    for (int i = 0; i < 32; i += 8) {
        int r = c0 + ty + i, c = r0 + tx;  // out is [C][R]
        if (r < C && c < R) out[(size_t)r * R + c] = tile[tx][ty + i];
    }
}

// C[M,N] = epilogue(A[M,K] @ B[K,N])
// EPI_TANH: tanh(acc + bias[n])
// EPI_DA2 : w3[n] * (1 - tanh(acc + bias[n])^2)
// EPI_MULT: acc * (1 - elem[m,n]^2)
// EPI_SYMP: symplectic permute + sign, write to out[M,64]
template <int BM, int BN, int BK, int TM, int TN, int EPI>
__global__ __launch_bounds__((BM / TM) * (BN / TN))
void gemm_epi(const float* __restrict__ A, const float* __restrict__ Bm,
              float* __restrict__ C,
              const float* __restrict__ bias, const float* __restrict__ w3,
              const float* __restrict__ elem,
              int M, int N, int K) {
    constexpr int NT = (BM / TM) * (BN / TN);
    __shared__ float As[BK][BM];
    __shared__ float Bs[BK][BN];

    const int m0 = blockIdx.y * BM, n0 = blockIdx.x * BN;
    const int tid = threadIdx.x;
    const int tidm = tid / (BN / TN);
    const int tidn = tid % (BN / TN);

    float acc[TM][TN];
#pragma unroll
    for (int i = 0; i < TM; i++)
#pragma unroll
        for (int j = 0; j < TN; j++) acc[i][j] = 0.f;

    for (int k0 = 0; k0 < K; k0 += BK) {
        // load A tile (store transposed into smem)
#pragma unroll
        for (int f = tid; f < BM * BK / 4; f += NT) {
            int row = f / (BK / 4);
            int k4 = (f % (BK / 4)) * 4;
            float4 v = *(const float4*)(A + (size_t)(m0 + row) * K + k0 + k4);
            As[k4 + 0][row] = v.x;
            As[k4 + 1][row] = v.y;
            As[k4 + 2][row] = v.z;
            As[k4 + 3][row] = v.w;
        }
        // load B tile
#pragma unroll
        for (int f = tid; f < BK * BN / 4; f += NT) {
            int kr = f / (BN / 4);
            int n4 = (f % (BN / 4)) * 4;
            *(float4*)&Bs[kr][n4] =
                *(const float4*)(Bm + (size_t)(k0 + kr) * N + n0 + n4);
        }
        __syncthreads();

#pragma unroll
        for (int k = 0; k < BK; k++) {
            float a[TM], b[TN];
#pragma unroll
            for (int v = 0; v < TM; v += 4)
                *(float4*)&a[v] = *(const float4*)&As[k][tidm * TM + v];
#pragma unroll
            for (int v = 0; v < TN; v += 4)
                *(float4*)&b[v] = *(const float4*)&Bs[k][tidn * TN + v];
#pragma unroll
            for (int i = 0; i < TM; i++)
#pragma unroll
                for (int j = 0; j < TN; j++) acc[i][j] += a[i] * b[j];
        }
        __syncthreads();
    }

    // epilogue
#pragma unroll
    for (int i = 0; i < TM; i++) {
        int m = m0 + tidm * TM + i;
#pragma unroll
        for (int j = 0; j < TN; j++) {
            int n = n0 + tidn * TN + j;
            float v = acc[i][j];
            if constexpr (EPI == EPI_TANH) {
                C[(size_t)m * N + n] = tanhf(v + bias[n]);
            } else if constexpr (EPI == EPI_DA2) {
                float t = tanhf(v + bias[n]);
                C[(size_t)m * N + n] = w3[n] * (1.f - t * t);
            } else if constexpr (EPI == EPI_MULT) {
                float e = elem[(size_t)m * N + n];
                C[(size_t)m * N + n] = v * (1.f - e * e);
            } else {  // EPI_SYMP
                int oc = (n + 32) & 63;
                float s = (n >= 32) ? 1.f : -1.f;
                C[(size_t)m * 64 + oc] = s * v;
            }
        }
    }
}

extern "C" void kernel_launch(void* const* d_in, const int* in_sizes, int n_in,
                              void* d_out, int out_size) {
    (void)in_sizes; (void)n_in; (void)out_size;
    // inputs: t, x, W0, b0, W1, b1, W2, b2, W3, b3
    const float* x  = (const float*)d_in[1];
    const float* W0 = (const float*)d_in[2];
    const float* b0 = (const float*)d_in[3];
    const float* W1 = (const float*)d_in[4];
    const float* b1 = (const float*)d_in[5];
    const float* W2 = (const float*)d_in[6];
    const float* b2 = (const float*)d_in[7];
    const float* W3 = (const float*)d_in[8];
    float* out = (float*)d_out;

    float *h0, *h1, *da, *db, *W1t, *W2t, *W0t;
    cudaGetSymbolAddress((void**)&h0, g_h0);
    cudaGetSymbolAddress((void**)&h1, g_h1);
    cudaGetSymbolAddress((void**)&da, g_da);
    cudaGetSymbolAddress((void**)&db, g_db);
    cudaGetSymbolAddress((void**)&W1t, g_W1t);
    cudaGetSymbolAddress((void**)&W2t, g_W2t);
    cudaGetSymbolAddress((void**)&W0t, g_W0t);

    dim3 tb(32, 8);
    transpose_k<<<dim3(HID / 32, HID / 32), tb>>>(W1, W1t, HID, HID);
    transpose_k<<<dim3(HID / 32, HID / 32), tb>>>(W2, W2t, HID, HID);
    transpose_k<<<dim3(HID / 32, (DIN + 31) / 32), tb>>>(W0, W0t, DIN, HID);

    dim3 g512(HID / 128, BATCH / 128);  // (4, 512)

    // Forward
    gemm_epi<128, 128, 16, 8, 8, EPI_TANH><<<g512, 256>>>(
        x, W0, h0, b0, nullptr, nullptr, BATCH, HID, DIN);
    gemm_epi<128, 128, 16, 8, 8, EPI_TANH><<<g512, 256>>>(
        h0, W1, h1, b1, nullptr, nullptr, BATCH, HID, HID);
    // da2 = W3 * (1 - tanh(h1@W2+b2)^2)
    gemm_epi<128, 128, 16, 8, 8, EPI_DA2><<<g512, 256>>>(
        h1, W2, da, b2, W3, nullptr, BATCH, HID, HID);
    // Backward
    // da1 = (da2 @ W2^T) * (1 - h1^2)
    gemm_epi<128, 128, 16, 8, 8, EPI_MULT><<<g512, 256>>>(
        da, W2t, db, nullptr, nullptr, h1, BATCH, HID, HID);
    // da0 = (da1 @ W1^T) * (1 - h0^2)
    gemm_epi<128, 128, 16, 8, 8, EPI_MULT><<<g512, 256>>>(
        db, W1t, da, nullptr, nullptr, h0, BATCH, HID, HID);
    // out = symplectic(da0 @ W0^T)
    gemm_epi<128, 64, 16, 8, 4, EPI_SYMP><<<dim3(1, BATCH / 128), 256>>>(
        da, W0t, out, nullptr, nullptr, nullptr, BATCH, DIN, HID);
}

// round 3
// speedup vs baseline: 1.9246x; 1.9246x over previous
#include <cuda_runtime.h>
#include <cuda_bf16.h>
#include <stdint.h>
#include <math.h>

typedef __nv_bfloat16 bf16;

#define BATCH 65536
#define DIN   64
#define HID   512

enum { EPI_TANH = 0, EPI_DA2 = 1, EPI_MULT = 2, EPI_SYMP = 3 };

// ---------------- scratch (__device__ globals; allocation-free rule) --------
// Activations: plain row-major [B][N] bf16, hi/lo pair (3xBF16 split).
__device__ bf16 g_a0h[(size_t)BATCH * DIN];
__device__ bf16 g_a0l[(size_t)BATCH * DIN];
__device__ bf16 g_h0h[(size_t)BATCH * HID];
__device__ bf16 g_h0l[(size_t)BATCH * HID];
__device__ bf16 g_h1h[(size_t)BATCH * HID];
__device__ bf16 g_h1l[(size_t)BATCH * HID];
__device__ bf16 g_d2h[(size_t)BATCH * HID];
__device__ bf16 g_d2l[(size_t)BATCH * HID];
__device__ bf16 g_d1h[(size_t)BATCH * HID];
__device__ bf16 g_d1l[(size_t)BATCH * HID];
__device__ bf16 g_d0h[(size_t)BATCH * HID];
__device__ bf16 g_d0l[(size_t)BATCH * HID];
// Weights as B-operand [N][K] row-major (K-major per output), hi/lo.
__device__ bf16 g_bf0h[HID * DIN];
__device__ bf16 g_bf0l[HID * DIN];
__device__ bf16 g_bf1h[HID * HID];
__device__ bf16 g_bf1l[HID * HID];
__device__ bf16 g_bf2h[HID * HID];
__device__ bf16 g_bf2l[HID * HID];
__device__ bf16 g_bb2h[HID * HID];
__device__ bf16 g_bb2l[HID * HID];
__device__ bf16 g_bb1h[HID * HID];
__device__ bf16 g_bb1l[HID * HID];
__device__ bf16 g_bb0h[DIN * HID];
__device__ bf16 g_bb0l[DIN * HID];

// ---------------- helpers ----------------------------------------------------
__device__ __forceinline__ uint32_t s2u(const void* p) {
    uint32_t a;
    asm("{ .reg .u64 t; cvta.to.shared.u64 t, %1; cvt.u32.u64 %0, t; }"
        : "=r"(a) : "l"(p));
    return a;
}
__device__ __forceinline__ void split_bf(float v, uint16_t& h, uint16_t& l) {
    bf16 hb = __float2bfloat16(v);
    bf16 lb = __float2bfloat16(v - __bfloat162float(hb));
    h = __bfloat16_as_ushort(hb);
    l = __bfloat16_as_ushort(lb);
}
__device__ __forceinline__ void cpa16(uint32_t dst, const void* src) {
    asm volatile("cp.async.cg.shared.global [%0], [%1], 16;" :: "r"(dst), "l"(src));
}
__device__ __forceinline__ void cp_commit() {
    asm volatile("cp.async.commit_group;" ::: "memory");
}
template <int N>
__device__ __forceinline__ void cp_wait() {
    asm volatile("cp.async.wait_group %0;" :: "n"(N) : "memory");
}
__device__ __forceinline__ void ldx4(uint32_t* r, uint32_t a) {
    asm volatile("ldmatrix.sync.aligned.m8n8.x4.shared.b16 {%0,%1,%2,%3}, [%4];"
                 : "=r"(r[0]), "=r"(r[1]), "=r"(r[2]), "=r"(r[3]) : "r"(a));
}
__device__ __forceinline__ void mma16816(float* c, const uint32_t* a,
                                         uint32_t b0, uint32_t b1) {
    asm volatile(
        "mma.sync.aligned.m16n8k16.row.col.f32.bf16.bf16.f32 "
        "{%0,%1,%2,%3}, {%4,%5,%6,%7}, {%8,%9}, {%0,%1,%2,%3};"
        : "+f"(c[0]), "+f"(c[1]), "+f"(c[2]), "+f"(c[3])
        : "r"(a[0]), "r"(a[1]), "r"(a[2]), "r"(a[3]), "r"(b0), "r"(b1));
}

// ---------------- conversion / packing ---------------------------------------
__global__ void convert_x(const float* __restrict__ x, bf16* __restrict__ hi,
                          bf16* __restrict__ lo, int n) {
    int t = blockIdx.x * 256 + threadIdx.x;
    if (t >= n) return;
    uint16_t h, l;
    split_bf(x[t], h, l);
    hi[t] = __ushort_as_bfloat16(h);
    lo[t] = __ushort_as_bfloat16(l);
}
// out[n][k] = TR ? W[k][n] (W is [K][N]) : W[n][k] (W is [N][K])
template <bool TR>
__global__ void pack_w(const float* __restrict__ W, int N, int K,
                       bf16* __restrict__ hi, bf16* __restrict__ lo) {
    int t = blockIdx.x * 256 + threadIdx.x;
    if (t >= N * K) return;
    int n = t / K, k = t % K;
    float v = TR ? W[(size_t)k * N + n] : W[(size_t)n * K + k];
    uint16_t h, l;
    split_bf(v, h, l);
    hi[t] = __ushort_as_bfloat16(h);
    lo[t] = __ushort_as_bfloat16(l);
}

// ---------------- HMMA GEMM with fused epilogue ------------------------------
// C[128 x NTILE] per CTA. 3xBF16 split via flattened (combo, kchunk) loop.
// smem tiles: rows x 32 bf16, 80B pitch (conflict-free ldmatrix).
template <int EPI, int NTILE>
__global__ void __launch_bounds__(256)
hnn_gemm(const bf16* __restrict__ Ah, const bf16* __restrict__ Al,
         const bf16* __restrict__ Bh, const bf16* __restrict__ Bl,
         const float* __restrict__ bias, const float* __restrict__ w3,
         const bf16* __restrict__ Hh, const bf16* __restrict__ Hl,
         bf16* __restrict__ Oh, bf16* __restrict__ Ol,
         float* __restrict__ Osym, int K, int NTOT) {
    constexpr int PITCH = 80;
    constexpr int ASZ = 128 * PITCH;
    constexpr int BSZ = NTILE * PITCH;
    constexpr int WM = (NTILE == 128) ? 2 : 4;  // warps along M
    constexpr int MI = 128 / (WM * 16);         // m16 tiles per warp
    extern __shared__ __align__(16) char smem[];
    const uint32_t sb = s2u(smem);

    const int tid = threadIdx.x;
    const int lane = tid & 31;
    const int w = tid >> 5;
    const int wm = w % WM, wn = w / WM;
    const int m0 = blockIdx.y * 128;
    const int n0 = blockIdx.x * NTILE;
    const int mbase = wm * MI * 16;
    const int nbase = wn * 32;

    const bf16* Asel[3] = {Ah, Ah, Al};
    const bf16* Bsel[3] = {Bh, Bl, Bh};
    const int KC = K >> 5;
    const int CT = 3 * KC;

    float acc[MI][4][4];
#pragma unroll
    for (int i = 0; i < MI; i++)
#pragma unroll
        for (int j = 0; j < 4; j++)
#pragma unroll
            for (int e = 0; e < 4; e++) acc[i][j][e] = 0.f;

    auto load_chunk = [&](int cc, int s) {
        const bf16* Ap = Asel[cc / KC];
        const bf16* Bp = Bsel[cc / KC];
        int k0 = (cc % KC) << 5;
        uint32_t aB = sb + s * (ASZ + BSZ);
        uint32_t bB = aB + ASZ;
#pragma unroll
        for (int i = 0; i < 2; i++) {
            int u = tid + i * 256;               // 512 units: row=u>>2, c=u&3
            int row = u >> 2, c = u & 3;
            cpa16(aB + row * PITCH + c * 16,
                  Ap + (size_t)(m0 + row) * K + k0 + c * 8);
        }
#pragma unroll
        for (int i = 0; i < NTILE / 64; i++) {
            int u = tid + i * 256;
            int row = u >> 2, c = u & 3;
            cpa16(bB + row * PITCH + c * 16,
                  Bp + (size_t)(n0 + row) * K + k0 + c * 8);
        }
        cp_commit();
    };

    load_chunk(0, 0);
    for (int cc = 0; cc < CT; cc++) {
        int s = cc & 1;
        if (cc + 1 < CT) {
            load_chunk(cc + 1, 1 - s);
            cp_wait<1>();
        } else {
            cp_wait<0>();
        }
        __syncthreads();
        uint32_t aB = sb + s * (ASZ + BSZ);
        uint32_t bB = aB + ASZ;
#pragma unroll
        for (int ks = 0; ks < 2; ks++) {
            uint32_t aF[MI][4], bF[2][4];
#pragma unroll
            for (int i = 0; i < MI; i++) {
                uint32_t addr = aB + (mbase + i * 16 + (lane & 15)) * PITCH +
                                ks * 32 + ((lane >> 4) << 4);
                ldx4(aF[i], addr);
            }
#pragma unroll
            for (int j = 0; j < 2; j++) {
                int row = nbase + j * 16 + ((lane >> 4) << 3) + (lane & 7);
                uint32_t addr = bB + row * PITCH + ks * 32 + (((lane >> 3) & 1) << 4);
                ldx4(bF[j], addr);
            }
#pragma unroll
            for (int i = 0; i < MI; i++)
#pragma unroll
                for (int nj = 0; nj < 4; nj++)
                    mma16816(acc[i][nj], aF[i], bF[nj >> 1][(nj & 1) * 2],
                             bF[nj >> 1][(nj & 1) * 2 + 1]);
        }
        __syncthreads();
    }

    // ---------------- epilogue ----------------
    const int qr = lane >> 2, qc = lane & 3;
#pragma unroll
    for (int i = 0; i < MI; i++) {
#pragma unroll
        for (int nj = 0; nj < 4; nj++) {
            int n = n0 + nbase + nj * 8 + qc * 2;
#pragma unroll
            for (int h = 0; h < 2; h++) {
                int m = m0 + mbase + i * 16 + qr + h * 8;
                float v0 = acc[i][nj][h * 2], v1 = acc[i][nj][h * 2 + 1];
                if constexpr (EPI == EPI_TANH) {
                    v0 = tanhf(v0 + __ldg(bias + n));
                    v1 = tanhf(v1 + __ldg(bias + n + 1));
                } else if constexpr (EPI == EPI_DA2) {
                    float t0 = tanhf(v0 + __ldg(bias + n));
                    float t1 = tanhf(v1 + __ldg(bias + n + 1));
                    v0 = __ldg(w3 + n) * (1.f - t0 * t0);
                    v1 = __ldg(w3 + n + 1) * (1.f - t1 * t1);
                } else if constexpr (EPI == EPI_MULT) {
                    size_t off = ((size_t)m * NTOT + n) * 2;
                    uint32_t uh = *(const uint32_t*)((const char*)Hh + off);
                    uint32_t ul = *(const uint32_t*)((const char*)Hl + off);
                    float h0 = __bfloat162float(__ushort_as_bfloat16((uint16_t)uh)) +
                               __bfloat162float(__ushort_as_bfloat16((uint16_t)ul));
                    float h1 = __bfloat162float(__ushort_as_bfloat16((uint16_t)(uh >> 16))) +
                               __bfloat162float(__ushort_as_bfloat16((uint16_t)(ul >> 16)));
                    v0 *= (1.f - h0 * h0);
                    v1 *= (1.f - h1 * h1);
                }
                if constexpr (EPI == EPI_SYMP) {
                    float sgn = (n >= 32) ? 1.f : -1.f;
                    *(float2*)(Osym + (size_t)m * 64 + (n ^ 32)) =
                        make_float2(sgn * v0, sgn * v1);
                } else {
                    uint16_t h0, l0, h1, l1;
                    split_bf(v0, h0, l0);
                    split_bf(v1, h1, l1);
                    size_t off = ((size_t)m * NTOT + n) * 2;
                    *(uint32_t*)((char*)Oh + off) = (uint32_t)h0 | ((uint32_t)h1 << 16);
                    *(uint32_t*)((char*)Ol + off) = (uint32_t)l0 | ((uint32_t)l1 << 16);
                }
            }
        }
    }
}

// ---------------- host -------------------------------------------------------
extern "C" void kernel_launch(void* const* d_in, const int* in_sizes, int n_in,
                              void* d_out, int out_size) {
    (void)in_sizes; (void)n_in; (void)out_size;
    const float* x  = (const float*)d_in[1];
    const float* W0 = (const float*)d_in[2];
    const float* b0 = (const float*)d_in[3];
    const float* W1 = (const float*)d_in[4];
    const float* b1 = (const float*)d_in[5];
    const float* W2 = (const float*)d_in[6];
    const float* b2 = (const float*)d_in[7];
    const float* W3 = (const float*)d_in[8];
    float* out = (float*)d_out;

    bf16 *a0h, *a0l, *h0h, *h0l, *h1h, *h1l, *d2h, *d2l, *d1h, *d1l, *d0h, *d0l;
    bf16 *bf0h, *bf0l, *bf1h, *bf1l, *bf2h, *bf2l, *bb2h, *bb2l, *bb1h, *bb1l, *bb0h, *bb0l;
    cudaGetSymbolAddress((void**)&a0h, g_a0h);  cudaGetSymbolAddress((void**)&a0l, g_a0l);
    cudaGetSymbolAddress((void**)&h0h, g_h0h);  cudaGetSymbolAddress((void**)&h0l, g_h0l);
    cudaGetSymbolAddress((void**)&h1h, g_h1h);  cudaGetSymbolAddress((void**)&h1l, g_h1l);
    cudaGetSymbolAddress((void**)&d2h, g_d2h);  cudaGetSymbolAddress((void**)&d2l, g_d2l);
    cudaGetSymbolAddress((void**)&d1h, g_d1h);  cudaGetSymbolAddress((void**)&d1l, g_d1l);
    cudaGetSymbolAddress((void**)&d0h, g_d0h);  cudaGetSymbolAddress((void**)&d0l, g_d0l);
    cudaGetSymbolAddress((void**)&bf0h, g_bf0h); cudaGetSymbolAddress((void**)&bf0l, g_bf0l);
    cudaGetSymbolAddress((void**)&bf1h, g_bf1h); cudaGetSymbolAddress((void**)&bf1l, g_bf1l);
    cudaGetSymbolAddress((void**)&bf2h, g_bf2h); cudaGetSymbolAddress((void**)&bf2l, g_bf2l);
    cudaGetSymbolAddress((void**)&bb2h, g_bb2h); cudaGetSymbolAddress((void**)&bb2l, g_bb2l);
    cudaGetSymbolAddress((void**)&bb1h, g_bb1h); cudaGetSymbolAddress((void**)&bb1l, g_bb1l);
    cudaGetSymbolAddress((void**)&bb0h, g_bb0h); cudaGetSymbolAddress((void**)&bb0l, g_bb0l);

    convert_x<<<(BATCH * DIN + 255) / 256, 256>>>(x, a0h, a0l, BATCH * DIN);
    pack_w<true><<<(HID * DIN + 255) / 256, 256>>>(W0, HID, DIN, bf0h, bf0l);
    pack_w<true><<<(HID * HID + 255) / 256, 256>>>(W1, HID, HID, bf1h, bf1l);
    pack_w<true><<<(HID * HID + 255) / 256, 256>>>(W2, HID, HID, bf2h, bf2l);
    pack_w<false><<<(HID * HID + 255) / 256, 256>>>(W2, HID, HID, bb2h, bb2l);
    pack_w<false><<<(HID * HID + 255) / 256, 256>>>(W1, HID, HID, bb1h, bb1l);
    pack_w<false><<<(DIN * HID + 255) / 256, 256>>>(W0, DIN, HID, bb0h, bb0l);

    constexpr int SM128 = 2 * (128 * 80 + 128 * 80);  // 40960
    constexpr int SM64  = 2 * (128 * 80 + 64 * 80);   // 30720
    dim3 g(HID / 128, BATCH / 128);  // (4, 512)

    // h0 = tanh(x @ W0 + b0)
    hnn_gemm<EPI_TANH, 128><<<g, 256, SM128>>>(a0h, a0l, bf0h, bf0l, b0, nullptr,
                                               nullptr, nullptr, h0h, h0l, nullptr, DIN, HID);
    // h1 = tanh(h0 @ W1 + b1)
    hnn_gemm<EPI_TANH, 128><<<g, 256, SM128>>>(h0h, h0l, bf1h, bf1l, b1, nullptr,
                                               nullptr, nullptr, h1h, h1l, nullptr, HID, HID);
    // d2 = W3 * (1 - tanh(h1 @ W2 + b2)^2)
    hnn_gemm<EPI_DA2, 128><<<g, 256, SM128>>>(h1h, h1l, bf2h, bf2l, b2, W3,
                                              nullptr, nullptr, d2h, d2l, nullptr, HID, HID);
    // d1 = (d2 @ W2^T) * (1 - h1^2)
    hnn_gemm<EPI_MULT, 128><<<g, 256, SM128>>>(d2h, d2l, bb2h, bb2l, nullptr, nullptr,
                                               h1h, h1l, d1h, d1l, nullptr, HID, HID);
    // d0 = (d1 @ W1^T) * (1 - h0^2)
    hnn_gemm<EPI_MULT, 128><<<g, 256, SM128>>>(d1h, d1l, bb1h, bb1l, nullptr, nullptr,
                                               h0h, h0l, d0h, d0l, nullptr, HID, HID);
    // out = symplectic(d0 @ W0^T)
    hnn_gemm<EPI_SYMP, 64><<<dim3(1, BATCH / 128), 256, SM64>>>(
        d0h, d0l, bb0h, bb0l, nullptr, nullptr, nullptr, nullptr,
        nullptr, nullptr, out, HID, DIN);
}

// round 4
// speedup vs baseline: 2.1359x; 1.1098x over previous
#include <cuda_runtime.h>
#include <cuda_bf16.h>
#include <stdint.h>
#include <math.h>

typedef __nv_bfloat16 bf16;

#define BATCH 65536
#define DIN   64
#define HID   512

enum { EPI_TANH = 0, EPI_DA2 = 1, EPI_MULT = 2, EPI_SYMP = 3 };

// ---------------- scratch (__device__ globals; allocation-free rule) --------
__device__ bf16 g_a0h[(size_t)BATCH * DIN];
__device__ bf16 g_a0l[(size_t)BATCH * DIN];
__device__ bf16 g_h0h[(size_t)BATCH * HID];
__device__ bf16 g_h0l[(size_t)BATCH * HID];
__device__ bf16 g_h1h[(size_t)BATCH * HID];
__device__ bf16 g_h1l[(size_t)BATCH * HID];
__device__ bf16 g_d2h[(size_t)BATCH * HID];
__device__ bf16 g_d2l[(size_t)BATCH * HID];
__device__ bf16 g_d1h[(size_t)BATCH * HID];
__device__ bf16 g_d1l[(size_t)BATCH * HID];
__device__ bf16 g_d0h[(size_t)BATCH * HID];
__device__ bf16 g_d0l[(size_t)BATCH * HID];
__device__ bf16 g_bf0h[HID * DIN];
__device__ bf16 g_bf0l[HID * DIN];
__device__ bf16 g_bf1h[HID * HID];
__device__ bf16 g_bf1l[HID * HID];
__device__ bf16 g_bf2h[HID * HID];
__device__ bf16 g_bf2l[HID * HID];
__device__ bf16 g_bb2h[HID * HID];
__device__ bf16 g_bb2l[HID * HID];
__device__ bf16 g_bb1h[HID * HID];
__device__ bf16 g_bb1l[HID * HID];
__device__ bf16 g_bb0h[DIN * HID];
__device__ bf16 g_bb0l[DIN * HID];

// ---------------- helpers ----------------------------------------------------
__device__ __forceinline__ uint32_t s2u(const void* p) {
    uint32_t a;
    asm("{ .reg .u64 t; cvta.to.shared.u64 t, %1; cvt.u32.u64 %0, t; }"
        : "=r"(a) : "l"(p));
    return a;
}
__device__ __forceinline__ void split_bf(float v, uint16_t& h, uint16_t& l) {
    bf16 hb = __float2bfloat16(v);
    bf16 lb = __float2bfloat16(v - __bfloat162float(hb));
    h = __bfloat16_as_ushort(hb);
    l = __bfloat16_as_ushort(lb);
}
__device__ __forceinline__ void cpa16(uint32_t dst, const void* src) {
    asm volatile("cp.async.cg.shared.global [%0], [%1], 16;" :: "r"(dst), "l"(src));
}
__device__ __forceinline__ void cp_commit() {
    asm volatile("cp.async.commit_group;" ::: "memory");
}
template <int N>
__device__ __forceinline__ void cp_wait() {
    asm volatile("cp.async.wait_group %0;" :: "n"(N) : "memory");
}
__device__ __forceinline__ void ldx4(uint32_t* r, uint32_t a) {
    asm volatile("ldmatrix.sync.aligned.m8n8.x4.shared.b16 {%0,%1,%2,%3}, [%4];"
                 : "=r"(r[0]), "=r"(r[1]), "=r"(r[2]), "=r"(r[3]) : "r"(a));
}
__device__ __forceinline__ void mma16816(float* c, const uint32_t* a,
                                         uint32_t b0, uint32_t b1) {
    asm volatile(
        "mma.sync.aligned.m16n8k16.row.col.f32.bf16.bf16.f32 "
        "{%0,%1,%2,%3}, {%4,%5,%6,%7}, {%8,%9}, {%0,%1,%2,%3};"
        : "+f"(c[0]), "+f"(c[1]), "+f"(c[2]), "+f"(c[3])
        : "r"(a[0]), "r"(a[1]), "r"(a[2]), "r"(a[3]), "r"(b0), "r"(b1));
}

// ---------------- conversion / packing ---------------------------------------
__global__ void convert_x(const float* __restrict__ x, bf16* __restrict__ hi,
                          bf16* __restrict__ lo, int n) {
    int t = blockIdx.x * 256 + threadIdx.x;
    if (t >= n) return;
    uint16_t h, l;
    split_bf(x[t], h, l);
    hi[t] = __ushort_as_bfloat16(h);
    lo[t] = __ushort_as_bfloat16(l);
}
template <bool TR>
__global__ void pack_w(const float* __restrict__ W, int N, int K,
                       bf16* __restrict__ hi, bf16* __restrict__ lo) {
    int t = blockIdx.x * 256 + threadIdx.x;
    if (t >= N * K) return;
    int n = t / K, k = t % K;
    float v = TR ? W[(size_t)k * N + n] : W[(size_t)n * K + k];
    uint16_t h, l;
    split_bf(v, h, l);
    hi[t] = __ushort_as_bfloat16(h);
    lo[t] = __ushort_as_bfloat16(l);
}

// ---------------- HMMA GEMM, shared-tile 3xBF16, 3-stage pipeline ------------
// CTA: 128 x NTILE, 512 threads, 16 warps. Per k-chunk (32): load Ah,Al,Bh,Bl
// once; run 3 MMA passes (AhBh, AhBl, AlBh). One __syncthreads per chunk.
template <int EPI, int NTILE>
__global__ void __launch_bounds__(512)
hnn_gemm(const bf16* __restrict__ Ah, const bf16* __restrict__ Al,
         const bf16* __restrict__ Bh, const bf16* __restrict__ Bl,
         const float* __restrict__ bias, const float* __restrict__ w3,
         const bf16* __restrict__ Hh, const bf16* __restrict__ Hl,
         bf16* __restrict__ Oh, bf16* __restrict__ Ol,
         float* __restrict__ Osym, int K, int NTOT) {
    constexpr int PITCH = 80;
    constexpr int ASZ = 128 * PITCH;          // one A tile (hi or lo)
    constexpr int BSZ = NTILE * PITCH;        // one B tile
    constexpr int STAGE = 2 * ASZ + 2 * BSZ;
    constexpr int WN = NTILE / 32;            // warps along N
    constexpr int WM = 16 / WN;               // warps along M
    constexpr int MI = 128 / (WM * 16);       // m16 tiles per warp

    extern __shared__ __align__(16) char smem[];
    const uint32_t sb = s2u(smem);

    const int tid = threadIdx.x;
    const int lane = tid & 31;
    const int w = tid >> 5;
    const int wm = w % WM, wn = w / WM;
    const int m0 = blockIdx.y * 128;
    const int n0 = blockIdx.x * NTILE;
    const int mbase = wm * (128 / WM);
    const int nbase = wn * 32;

    const int KC = K >> 5;

    float acc[MI][4][4];
#pragma unroll
    for (int i = 0; i < MI; i++)
#pragma unroll
        for (int j = 0; j < 4; j++)
#pragma unroll
            for (int e = 0; e < 4; e++) acc[i][j][e] = 0.f;

    const int arow = tid >> 2, ac = tid & 3;

    auto load_chunk = [&](int cc, int st) {
        int k0 = cc << 5;
        uint32_t base = sb + st * STAGE;
        cpa16(base + arow * PITCH + ac * 16,
              Ah + (size_t)(m0 + arow) * K + k0 + ac * 8);
        cpa16(base + ASZ + arow * PITCH + ac * 16,
              Al + (size_t)(m0 + arow) * K + k0 + ac * 8);
        if (NTILE == 128 || tid < NTILE * 4) {
            cpa16(base + 2 * ASZ + arow * PITCH + ac * 16,
                  Bh + (size_t)(n0 + arow) * K + k0 + ac * 8);
            cpa16(base + 2 * ASZ + BSZ + arow * PITCH + ac * 16,
                  Bl + (size_t)(n0 + arow) * K + k0 + ac * 8);
        }
        cp_commit();
    };

    load_chunk(0, 0);
    if (KC > 1) load_chunk(1, 1);

    for (int i = 0; i < KC; i++) {
        if (i + 1 < KC) cp_wait<1>(); else cp_wait<0>();
        __syncthreads();
        if (i + 2 < KC) load_chunk(i + 2, (i + 2) % 3);

        uint32_t base = sb + (i % 3) * STAGE;
        uint32_t aBh = base, aBl = base + ASZ;
        uint32_t bBh = base + 2 * ASZ, bBl = bBh + BSZ;
#pragma unroll
        for (int ks = 0; ks < 2; ks++) {
            const uint32_t aoff = (lane & 15) * PITCH + ks * 32 + ((lane >> 4) << 4);
            const uint32_t boff =
                (((lane >> 4) << 3) + (lane & 7)) * PITCH + ks * 32 +
                (((lane >> 3) & 1) << 4);
            uint32_t aFh[MI][4], aFl[MI][4], bFh[2][4], bFl[2][4];
#pragma unroll
            for (int ii = 0; ii < MI; ii++)
                ldx4(aFh[ii], aBh + (mbase + ii * 16) * PITCH + aoff);
#pragma unroll
            for (int j = 0; j < 2; j++)
                ldx4(bFh[j], bBh + (nbase + j * 16) * PITCH + boff);
            // pass 1: Ah * Bh
#pragma unroll
            for (int ii = 0; ii < MI; ii++)
#pragma unroll
                for (int nj = 0; nj < 4; nj++)
                    mma16816(acc[ii][nj], aFh[ii], bFh[nj >> 1][(nj & 1) * 2],
                             bFh[nj >> 1][(nj & 1) * 2 + 1]);
            // pass 2: Al * Bh
#pragma unroll
            for (int ii = 0; ii < MI; ii++)
                ldx4(aFl[ii], aBl + (mbase + ii * 16) * PITCH + aoff);
#pragma unroll
            for (int ii = 0; ii < MI; ii++)
#pragma unroll
                for (int nj = 0; nj < 4; nj++)
                    mma16816(acc[ii][nj], aFl[ii], bFh[nj >> 1][(nj & 1) * 2],
                             bFh[nj >> 1][(nj & 1) * 2 + 1]);
            // pass 3: Ah * Bl
#pragma unroll
            for (int j = 0; j < 2; j++)
                ldx4(bFl[j], bBl + (nbase + j * 16) * PITCH + boff);
#pragma unroll
            for (int ii = 0; ii < MI; ii++)
#pragma unroll
                for (int nj = 0; nj < 4; nj++)
                    mma16816(acc[ii][nj], aFh[ii], bFl[nj >> 1][(nj & 1) * 2],
                             bFl[nj >> 1][(nj & 1) * 2 + 1]);
        }
    }

    // ---------------- epilogue ----------------
    const int qr = lane >> 2, qc = lane & 3;
#pragma unroll
    for (int i = 0; i < MI; i++) {
#pragma unroll
        for (int nj = 0; nj < 4; nj++) {
            int n = n0 + nbase + nj * 8 + qc * 2;
#pragma unroll
            for (int h = 0; h < 2; h++) {
                int m = m0 + mbase + i * 16 + qr + h * 8;
                float v0 = acc[i][nj][h * 2], v1 = acc[i][nj][h * 2 + 1];
                if constexpr (EPI == EPI_TANH) {
                    v0 = tanhf(v0 + __ldg(bias + n));
                    v1 = tanhf(v1 + __ldg(bias + n + 1));
                } else if constexpr (EPI == EPI_DA2) {
                    float t0 = tanhf(v0 + __ldg(bias + n));
                    float t1 = tanhf(v1 + __ldg(bias + n + 1));
                    v0 = __ldg(w3 + n) * (1.f - t0 * t0);
                    v1 = __ldg(w3 + n + 1) * (1.f - t1 * t1);
                } else if constexpr (EPI == EPI_MULT) {
                    size_t off = ((size_t)m * NTOT + n) * 2;
                    uint32_t uh = *(const uint32_t*)((const char*)Hh + off);
                    uint32_t ul = *(const uint32_t*)((const char*)Hl + off);
                    float h0 = __bfloat162float(__ushort_as_bfloat16((uint16_t)uh)) +
                               __bfloat162float(__ushort_as_bfloat16((uint16_t)ul));
                    float h1 = __bfloat162float(__ushort_as_bfloat16((uint16_t)(uh >> 16))) +
                               __bfloat162float(__ushort_as_bfloat16((uint16_t)(ul >> 16)));
                    v0 *= (1.f - h0 * h0);
                    v1 *= (1.f - h1 * h1);
                }
                if constexpr (EPI == EPI_SYMP) {
                    float sgn = (n >= 32) ? 1.f : -1.f;
                    *(float2*)(Osym + (size_t)m * 64 + (n ^ 32)) =
                        make_float2(sgn * v0, sgn * v1);
                } else {
                    uint16_t h0, l0, h1, l1;
                    split_bf(v0, h0, l0);
                    split_bf(v1, h1, l1);
                    size_t off = ((size_t)m * NTOT + n) * 2;
                    *(uint32_t*)((char*)Oh + off) = (uint32_t)h0 | ((uint32_t)h1 << 16);
                    *(uint32_t*)((char*)Ol + off) = (uint32_t)l0 | ((uint32_t)l1 << 16);
                }
            }
        }
    }
}

// ---------------- host -------------------------------------------------------
extern "C" void kernel_launch(void* const* d_in, const int* in_sizes, int n_in,
                              void* d_out, int out_size) {
    (void)in_sizes; (void)n_in; (void)out_size;
    const float* x  = (const float*)d_in[1];
    const float* W0 = (const float*)d_in[2];
    const float* b0 = (const float*)d_in[3];
    const float* W1 = (const float*)d_in[4];
    const float* b1 = (const float*)d_in[5];
    const float* W2 = (const float*)d_in[6];
    const float* b2 = (const float*)d_in[7];
    const float* W3 = (const float*)d_in[8];
    float* out = (float*)d_out;

    bf16 *a0h, *a0l, *h0h, *h0l, *h1h, *h1l, *d2h, *d2l, *d1h, *d1l, *d0h, *d0l;
    bf16 *bf0h, *bf0l, *bf1h, *bf1l, *bf2h, *bf2l, *bb2h, *bb2l, *bb1h, *bb1l, *bb0h, *bb0l;
    cudaGetSymbolAddress((void**)&a0h, g_a0h);  cudaGetSymbolAddress((void**)&a0l, g_a0l);
    cudaGetSymbolAddress((void**)&h0h, g_h0h);  cudaGetSymbolAddress((void**)&h0l, g_h0l);
    cudaGetSymbolAddress((void**)&h1h, g_h1h);  cudaGetSymbolAddress((void**)&h1l, g_h1l);
    cudaGetSymbolAddress((void**)&d2h, g_d2h);  cudaGetSymbolAddress((void**)&d2l, g_d2l);
    cudaGetSymbolAddress((void**)&d1h, g_d1h);  cudaGetSymbolAddress((void**)&d1l, g_d1l);
    cudaGetSymbolAddress((void**)&d0h, g_d0h);  cudaGetSymbolAddress((void**)&d0l, g_d0l);
    cudaGetSymbolAddress((void**)&bf0h, g_bf0h); cudaGetSymbolAddress((void**)&bf0l, g_bf0l);
    cudaGetSymbolAddress((void**)&bf1h, g_bf1h); cudaGetSymbolAddress((void**)&bf1l, g_bf1l);
    cudaGetSymbolAddress((void**)&bf2h, g_bf2h); cudaGetSymbolAddress((void**)&bf2l, g_bf2l);
    cudaGetSymbolAddress((void**)&bb2h, g_bb2h); cudaGetSymbolAddress((void**)&bb2l, g_bb2l);
    cudaGetSymbolAddress((void**)&bb1h, g_bb1h); cudaGetSymbolAddress((void**)&bb1l, g_bb1l);
    cudaGetSymbolAddress((void**)&bb0h, g_bb0h); cudaGetSymbolAddress((void**)&bb0l, g_bb0l);

    convert_x<<<(BATCH * DIN + 255) / 256, 256>>>(x, a0h, a0l, BATCH * DIN);
    pack_w<true><<<(HID * DIN + 255) / 256, 256>>>(W0, HID, DIN, bf0h, bf0l);
    pack_w<true><<<(HID * HID + 255) / 256, 256>>>(W1, HID, HID, bf1h, bf1l);
    pack_w<true><<<(HID * HID + 255) / 256, 256>>>(W2, HID, HID, bf2h, bf2l);
    pack_w<false><<<(HID * HID + 255) / 256, 256>>>(W2, HID, HID, bb2h, bb2l);
    pack_w<false><<<(HID * HID + 255) / 256, 256>>>(W1, HID, HID, bb1h, bb1l);
    pack_w<false><<<(DIN * HID + 255) / 256, 256>>>(W0, DIN, HID, bb0h, bb0l);

    constexpr int ST128 = 2 * 128 * 80 + 2 * 128 * 80;  // 40960
    constexpr int ST64  = 2 * 128 * 80 + 2 * 64 * 80;   // 30720
    constexpr int SM128 = 3 * ST128;  // 122880
    constexpr int SM64  = 3 * ST64;   // 92160
    cudaFuncSetAttribute(hnn_gemm<EPI_TANH, 128>, cudaFuncAttributeMaxDynamicSharedMemorySize, SM128);
    cudaFuncSetAttribute(hnn_gemm<EPI_DA2, 128>,  cudaFuncAttributeMaxDynamicSharedMemorySize, SM128);
    cudaFuncSetAttribute(hnn_gemm<EPI_MULT, 128>, cudaFuncAttributeMaxDynamicSharedMemorySize, SM128);
    cudaFuncSetAttribute(hnn_gemm<EPI_SYMP, 64>,  cudaFuncAttributeMaxDynamicSharedMemorySize, SM64);

    dim3 g(HID / 128, BATCH / 128);  // (4, 512)

    hnn_gemm<EPI_TANH, 128><<<g, 512, SM128>>>(a0h, a0l, bf0h, bf0l, b0, nullptr,
                                               nullptr, nullptr, h0h, h0l, nullptr, DIN, HID);
    hnn_gemm<EPI_TANH, 128><<<g, 512, SM128>>>(h0h, h0l, bf1h, bf1l, b1, nullptr,
                                               nullptr, nullptr, h1h, h1l, nullptr, HID, HID);
    hnn_gemm<EPI_DA2, 128><<<g, 512, SM128>>>(h1h, h1l, bf2h, bf2l, b2, W3,
                                              nullptr, nullptr, d2h, d2l, nullptr, HID, HID);
    hnn_gemm<EPI_MULT, 128><<<g, 512, SM128>>>(d2h, d2l, bb2h, bb2l, nullptr, nullptr,
                                               h1h, h1l, d1h, d1l, nullptr, HID, HID);
    hnn_gemm<EPI_MULT, 128><<<g, 512, SM128>>>(d1h, d1l, bb1h, bb1l, nullptr, nullptr,
                                               h0h, h0l, d0h, d0l, nullptr, HID, HID);
    hnn_gemm<EPI_SYMP, 64><<<dim3(1, BATCH / 128), 512, SM64>>>(
        d0h, d0l, bb0h, bb0l, nullptr, nullptr, nullptr, nullptr,
        nullptr, nullptr, out, HID, DIN);
}